// round 17
// baseline (speedup 1.0000x reference)
#include <cuda_runtime.h>
#include <cuda_bf16.h>
#include <math.h>
#include <stdint.h>

#define NN  12288
#define NE  393216
#define FIN 256
#define FH  128
#define FZ  64

// ---------------- scratch (no allocs allowed) ----------------
__device__ int   g_deg[NN];          // zero-initialized; k_scan restores zero each call
__device__ float g_norm[NN];
__device__ int   g_rowptr[NN + 1];
__device__ int   g_cursor[NN];
__device__ int   g_csrc[NE];
__device__ float g_H1[NN * FH];
__device__ float g_hidden[NN * FH];
__device__ float g_MS[NN * FH];
__device__ __align__(16) signed char g_Zq[NN * 128];  // [hi(64)|lo(64)] int8 per row
__device__ float g_Zs[NN];                            // per-row scale s
__device__ int   g_is64 = 1;

// ---------------- f32x2 packed-FMA helpers (prologue GEMMs) ----------------
__device__ __forceinline__ unsigned long long ffma2(unsigned long long a,
                                                    unsigned long long b,
                                                    unsigned long long c) {
    unsigned long long d;
    asm("fma.rn.f32x2 %0, %1, %2, %3;" : "=l"(d) : "l"(a), "l"(b), "l"(c));
    return d;
}
__device__ __forceinline__ unsigned long long pack2(float x, float y) {
    unsigned long long d;
    asm("mov.b64 %0, {%1, %2};" : "=l"(d) : "f"(x), "f"(y));
    return d;
}
__device__ __forceinline__ float2 unpack2(unsigned long long v) {
    float2 r;
    asm("mov.b64 {%0, %1}, %2;" : "=f"(r.x), "=f"(r.y) : "l"(v));
    return r;
}

__device__ __forceinline__ uint32_t smem_u32(const void* p) {
    uint32_t a;
    asm("{ .reg .u64 t; cvta.to.shared.u64 t, %1; cvt.u32.u64 %0, t; }" : "=r"(a) : "l"(p));
    return a;
}
#define CP_ASYNC16(dst, src) \
    asm volatile("cp.async.cg.shared.global [%0], [%1], 16;" :: "r"(dst), "l"(src))
#define CP_COMMIT() asm volatile("cp.async.commit_group;" ::: "memory")
#define CP_WAIT(n)  asm volatile("cp.async.wait_group %0;" :: "n"(n) : "memory")

// ---------------- init: dtype detect only ----------------
__global__ void k_init(const int* __restrict__ ei32) {
    int nz = (ei32[threadIdx.x * 2 + 1] != 0);
    unsigned m = __ballot_sync(0xffffffffu, nz);
    if (threadIdx.x == 0) g_is64 = (m == 0) ? 1 : 0;
}

__device__ __forceinline__ int load_idx(const void* ei, int pos) {
    if (g_is64) return (int)((const long long*)ei)[pos];
    return ((const int*)ei)[pos];
}

__global__ void k_count(const void* __restrict__ ei) {
    int e = blockIdx.x * blockDim.x + threadIdx.x;
    if (e < NE) atomicAdd(&g_deg[load_idx(ei, NE + e)], 1);
}

__global__ void k_scan() {
    __shared__ int wsum[32];
    int t = threadIdx.x, lane = t & 31, w = t >> 5;
    int warpBase = w * 384;
    int vals[12], excl[12];
#pragma unroll
    for (int k = 0; k < 12; k++) vals[k] = g_deg[warpBase + k * 32 + lane];
    int run = 0;
#pragma unroll
    for (int k = 0; k < 12; k++) {
        int d = vals[k];
        int v = d;
#pragma unroll
        for (int off = 1; off < 32; off <<= 1) {
            int u = __shfl_up_sync(0xffffffffu, v, off);
            if (lane >= off) v += u;
        }
        excl[k] = run + v - d;
        run += __shfl_sync(0xffffffffu, v, 31);
    }
    if (lane == 0) wsum[w] = run;
    __syncthreads();
    if (w == 0) {
        int x = wsum[lane];
#pragma unroll
        for (int off = 1; off < 32; off <<= 1) {
            int u = __shfl_up_sync(0xffffffffu, x, off);
            if (lane >= off) x += u;
        }
        wsum[lane] = x;
    }
    __syncthreads();
    int base = w ? wsum[w - 1] : 0;
#pragma unroll
    for (int k = 0; k < 12; k++) {
        int idx = warpBase + k * 32 + lane;
        int p = base + excl[k];
        g_rowptr[idx] = p;
        g_cursor[idx] = p;
        int d = vals[k];
        g_norm[idx] = rsqrtf((float)(d > 1 ? d : 1));
        g_deg[idx] = 0;
    }
    if (t == 1023) g_rowptr[NN] = wsum[31];
}

__global__ void k_fill(const void* __restrict__ ei) {
    int e = blockIdx.x * blockDim.x + threadIdx.x;
    if (e < NE) {
        int d = load_idx(ei, NE + e);
        int pos = atomicAdd(&g_cursor[d], 1);
        g_csrc[pos] = load_idx(ei, e);
    }
}

// ---------------- dense GEMM [M,K] x [K,128], FFMA2 ----------------
template <int K, int MODE>
__global__ void __launch_bounds__(256) k_gemm_norm(const float* __restrict__ Ain,
                                                   const float* __restrict__ Bin) {
    __shared__ float As[32][68];
    __shared__ float Bs[32][132];
    const float* A = (MODE == 0) ? Ain : g_hidden;
    float*       C = (MODE == 0) ? g_H1 : g_MS;

    int tid = threadIdx.x;
    int tx = tid & 15, ty = tid >> 4;
    int rowBase = blockIdx.x * 64;

    unsigned long long acc2[4][4];
#pragma unroll
    for (int i = 0; i < 4; i++)
#pragma unroll
        for (int q = 0; q < 4; q++) acc2[i][q] = 0ULL;

    for (int kc = 0; kc < K; kc += 32) {
#pragma unroll
        for (int i = 0; i < 2; i++) {
            int slot = tid + i * 256;
            int r = slot >> 3, c4 = slot & 7;
            float4 v = *(const float4*)&A[(size_t)(rowBase + r) * K + kc + c4 * 4];
            As[c4 * 4 + 0][r] = v.x; As[c4 * 4 + 1][r] = v.y;
            As[c4 * 4 + 2][r] = v.z; As[c4 * 4 + 3][r] = v.w;
        }
#pragma unroll
        for (int i = 0; i < 4; i++) {
            int slot = tid + i * 256;
            int r = slot >> 5, c4 = slot & 31;
            if (MODE == 0) {
                *(float4*)&Bs[r][c4 * 4] = *(const float4*)&Bin[(kc + r) * 128 + c4 * 4];
            } else {
                const float* srcp = (c4 < 16) ? Ain : Bin;
                int jj = (c4 & 15) * 4;
                *(float4*)&Bs[r][c4 * 4] = *(const float4*)&srcp[(kc + r) * 64 + jj];
            }
        }
        __syncthreads();
#pragma unroll
        for (int k = 0; k < 32; k++) {
            float4 av = *(const float4*)&As[k][ty * 4];
            unsigned long long a2[4];
            a2[0] = pack2(av.x, av.x); a2[1] = pack2(av.y, av.y);
            a2[2] = pack2(av.z, av.z); a2[3] = pack2(av.w, av.w);
            unsigned long long b2[4];
#pragma unroll
            for (int q = 0; q < 4; q++)
                b2[q] = *(const unsigned long long*)&Bs[k][tx * 8 + 2 * q];
#pragma unroll
            for (int i = 0; i < 4; i++)
#pragma unroll
                for (int q = 0; q < 4; q++) acc2[i][q] = ffma2(a2[i], b2[q], acc2[i][q]);
        }
        __syncthreads();
    }
#pragma unroll
    for (int i = 0; i < 4; i++) {
        int r = rowBase + ty * 4 + i;
        float nm = (MODE == 0) ? 1.0f : g_norm[r];
        float o[8];
#pragma unroll
        for (int q = 0; q < 4; q++) {
            float2 f = unpack2(acc2[i][q]);
            o[2 * q] = f.x * nm;
            o[2 * q + 1] = f.y * nm;
        }
        float* op = &C[(size_t)r * 128 + tx * 8];
        *(float4*)&op[0] = make_float4(o[0], o[1], o[2], o[3]);
        *(float4*)&op[4] = make_float4(o[4], o[5], o[6], o[7]);
    }
}

// ---------------- gather aggregation (warp per node, 4 chains) ----------------
__global__ void k_agg1() {
    int gw = (blockIdx.x * blockDim.x + threadIdx.x) >> 5;
    if (gw >= NN) return;
    int lane = threadIdx.x & 31;
    int s0 = g_rowptr[gw], s1 = g_rowptr[gw + 1];
    float4 ac0 = make_float4(0.f, 0.f, 0.f, 0.f);
    float4 ac1 = make_float4(0.f, 0.f, 0.f, 0.f);
    float4 ac2 = make_float4(0.f, 0.f, 0.f, 0.f);
    float4 ac3 = make_float4(0.f, 0.f, 0.f, 0.f);
    int e = s0;
    for (; e + 3 < s1; e += 4) {
        int a = g_csrc[e], b = g_csrc[e + 1], c = g_csrc[e + 2], d = g_csrc[e + 3];
        float na = g_norm[a], nb = g_norm[b], nc = g_norm[c], nd = g_norm[d];
        float4 va = *(const float4*)&g_H1[(size_t)a * FH + lane * 4];
        float4 vb = *(const float4*)&g_H1[(size_t)b * FH + lane * 4];
        float4 vc = *(const float4*)&g_H1[(size_t)c * FH + lane * 4];
        float4 vd = *(const float4*)&g_H1[(size_t)d * FH + lane * 4];
        ac0.x = fmaf(va.x, na, ac0.x); ac0.y = fmaf(va.y, na, ac0.y);
        ac0.z = fmaf(va.z, na, ac0.z); ac0.w = fmaf(va.w, na, ac0.w);
        ac1.x = fmaf(vb.x, nb, ac1.x); ac1.y = fmaf(vb.y, nb, ac1.y);
        ac1.z = fmaf(vb.z, nb, ac1.z); ac1.w = fmaf(vb.w, nb, ac1.w);
        ac2.x = fmaf(vc.x, nc, ac2.x); ac2.y = fmaf(vc.y, nc, ac2.y);
        ac2.z = fmaf(vc.z, nc, ac2.z); ac2.w = fmaf(vc.w, nc, ac2.w);
        ac3.x = fmaf(vd.x, nd, ac3.x); ac3.y = fmaf(vd.y, nd, ac3.y);
        ac3.z = fmaf(vd.z, nd, ac3.z); ac3.w = fmaf(vd.w, nd, ac3.w);
    }
    for (; e < s1; e++) {
        int a = g_csrc[e];
        float na = g_norm[a];
        float4 va = *(const float4*)&g_H1[(size_t)a * FH + lane * 4];
        ac0.x = fmaf(va.x, na, ac0.x); ac0.y = fmaf(va.y, na, ac0.y);
        ac0.z = fmaf(va.z, na, ac0.z); ac0.w = fmaf(va.w, na, ac0.w);
    }
    float nm = g_norm[gw];
    *(float4*)&g_hidden[(size_t)gw * FH + lane * 4] =
        make_float4((ac0.x + ac1.x + ac2.x + ac3.x) * nm,
                    (ac0.y + ac1.y + ac2.y + ac3.y) * nm,
                    (ac0.z + ac1.z + ac2.z + ac3.z) * nm,
                    (ac0.w + ac1.w + ac2.w + ac3.w) * nm);
}

// aggregate MS, post-norm, relu, reparameterize, quantize to int8 [hi|lo] + scale
__global__ void k_agg2z(const float* __restrict__ noise) {
    __shared__ float sm[8][128];
    int wl = threadIdx.x >> 5;
    int gw = (blockIdx.x * blockDim.x + threadIdx.x) >> 5;
    if (gw >= NN) return;
    int lane = threadIdx.x & 31;
    int s0 = g_rowptr[gw], s1 = g_rowptr[gw + 1];
    float4 ac0 = make_float4(0.f, 0.f, 0.f, 0.f);
    float4 ac1 = make_float4(0.f, 0.f, 0.f, 0.f);
    int e = s0;
    for (; e + 3 < s1; e += 4) {
        int a = g_csrc[e], b = g_csrc[e + 1], c = g_csrc[e + 2], d = g_csrc[e + 3];
        float4 va = *(const float4*)&g_MS[(size_t)a * FH + lane * 4];
        float4 vb = *(const float4*)&g_MS[(size_t)b * FH + lane * 4];
        float4 vc = *(const float4*)&g_MS[(size_t)c * FH + lane * 4];
        float4 vd = *(const float4*)&g_MS[(size_t)d * FH + lane * 4];
        ac0.x += va.x + vb.x; ac0.y += va.y + vb.y;
        ac0.z += va.z + vb.z; ac0.w += va.w + vb.w;
        ac1.x += vc.x + vd.x; ac1.y += vc.y + vd.y;
        ac1.z += vc.z + vd.z; ac1.w += vc.w + vd.w;
    }
    for (; e < s1; e++) {
        int a = g_csrc[e];
        float4 va = *(const float4*)&g_MS[(size_t)a * FH + lane * 4];
        ac0.x += va.x; ac0.y += va.y; ac0.z += va.z; ac0.w += va.w;
    }
    float nm = g_norm[gw];
    sm[wl][lane * 4 + 0] = fmaxf((ac0.x + ac1.x) * nm, 0.f);
    sm[wl][lane * 4 + 1] = fmaxf((ac0.y + ac1.y) * nm, 0.f);
    sm[wl][lane * 4 + 2] = fmaxf((ac0.z + ac1.z) * nm, 0.f);
    sm[wl][lane * 4 + 3] = fmaxf((ac0.w + ac1.w) * nm, 0.f);
    __syncwarp();

    float z[4] = {0.f, 0.f, 0.f, 0.f};
    float m = 0.f;
    if (lane < 16) {
        int j = lane * 4;
        float4 nz = *(const float4*)&noise[(size_t)gw * FZ + j];
        z[0] = fmaf(nz.x, expf(sm[wl][64 + j + 0]), sm[wl][j + 0]);
        z[1] = fmaf(nz.y, expf(sm[wl][64 + j + 1]), sm[wl][j + 1]);
        z[2] = fmaf(nz.z, expf(sm[wl][64 + j + 2]), sm[wl][j + 2]);
        z[3] = fmaf(nz.w, expf(sm[wl][64 + j + 3]), sm[wl][j + 3]);
        m = fmaxf(fmaxf(fabsf(z[0]), fabsf(z[1])), fmaxf(fabsf(z[2]), fabsf(z[3])));
    }
    // max over the 16-lane half (offsets <= 8 stay within the half)
#pragma unroll
    for (int off = 8; off >= 1; off >>= 1)
        m = fmaxf(m, __shfl_xor_sync(0xffffffffu, m, off));

    if (lane < 16) {
        float ms = fmaxf(m, 1e-20f);
        float s = ms * (1.0f / 127.0f);
        float inv = 127.0f / ms;  // == 1/s
        signed char hi[4], lo[4];
#pragma unroll
        for (int q = 0; q < 4; q++) {
            int ih = __float2int_rn(z[q] * inv);
            ih = max(-127, min(127, ih));
            float r = z[q] - (float)ih * s;
            int il = __float2int_rn(r * inv * 256.0f);
            il = max(-127, min(127, il));
            hi[q] = (signed char)ih;
            lo[q] = (signed char)il;
        }
        int j = lane * 4;
        *(char4*)&g_Zq[(size_t)gw * 128 + j]      = *(char4*)&hi[0];
        *(char4*)&g_Zq[(size_t)gw * 128 + 64 + j] = *(char4*)&lo[0];
        if (lane == 0) g_Zs[gw] = s;
    }
}

// ---------------- Z @ Z^T via mma.sync int8 (IMMA), split-precision ----------------
// Block tile: 128 rows x 64 cols. 8 warps 4(m) x 2(n), warp 32x32.
// Rows stored [hi(64)|lo(64)] int8. 6 k32-steps:
//   acc1: hi.hi  (ka,kb) = (0,0),(32,32)
//   acc2: hi.lo  (0,64),(32,96);  lo.hi (64,0),(96,32)
// out = sA[r]*sB[c]*(acc1 + acc2/256)
#define ZSB 144        // smem row stride in bytes
#define SM_A 0
#define SM_B (128 * ZSB)               // 18432
#define SM_SA (SM_B + 64 * ZSB)        // 27648
#define SM_SB (SM_SA + 128 * 4)        // 28160
#define SM_TOT (SM_SB + 64 * 4)        // 28416
#define NTRI8 9312  // sum over by of (192 - 2*by)

__device__ __forceinline__ void ldsm_x4(uint32_t addr, uint32_t& r0, uint32_t& r1,
                                        uint32_t& r2, uint32_t& r3) {
    asm volatile("ldmatrix.sync.aligned.m8n8.x4.shared.b16 {%0,%1,%2,%3}, [%4];"
                 : "=r"(r0), "=r"(r1), "=r"(r2), "=r"(r3) : "r"(addr));
}
__device__ __forceinline__ void imma16832(int* d, uint32_t a0, uint32_t a1,
                                          uint32_t a2, uint32_t a3, uint32_t b0,
                                          uint32_t b1) {
    asm volatile(
        "mma.sync.aligned.m16n8k32.row.col.s32.s8.s8.s32 "
        "{%0,%1,%2,%3}, {%4,%5,%6,%7}, {%8,%9}, {%0,%1,%2,%3};"
        : "+r"(d[0]), "+r"(d[1]), "+r"(d[2]), "+r"(d[3])
        : "r"(a0), "r"(a1), "r"(a2), "r"(a3), "r"(b0), "r"(b1));
}

__global__ void __launch_bounds__(256, 2) k_zzt_imma(float* __restrict__ out) {
    // decode: row-block by (128 rows) has (192 - 2*by) col-blocks (64 cols),
    // starting at bx = 2*by. C(by) = by*(193-by).
    int t = blockIdx.x;
    int by = (int)((193.0f - sqrtf(fmaf(-4.0f, (float)t, 193.0f * 193.0f))) * 0.5f);
    while (by * (193 - by) > t) by--;
    while ((by + 1) * (192 - by) <= t) by++;
    const int bx = 2 * by + (t - by * (193 - by));

    extern __shared__ char zsm[];
    const int tid = threadIdx.x;
    const int lane = tid & 31, wid = tid >> 5;
    const int wm = wid & 3, wn = wid >> 2;
    const int rowBase = by * 128;
    const int colBase = bx * 64;
    uint32_t sb = smem_u32(zsm);

    // group 0: hi bytes [0,64) of A (128 rows) and B (64 rows)
    {
        int r = tid >> 1, off = (tid & 1) * 32;
        const char* srcA = (const char*)&g_Zq[(size_t)(rowBase + r) * 128 + off];
        uint32_t dstA = sb + SM_A + r * ZSB + off;
        CP_ASYNC16(dstA, srcA);
        CP_ASYNC16(dstA + 16, srcA + 16);
        int rb = tid >> 2, offb = (tid & 3) * 16;
        const char* srcB = (const char*)&g_Zq[(size_t)(colBase + rb) * 128 + offb];
        CP_ASYNC16(sb + SM_B + rb * ZSB + offb, srcB);
    }
    CP_COMMIT();
    // group 1: lo bytes [64,128)
    {
        int r = tid >> 1, off = (tid & 1) * 32;
        const char* srcA = (const char*)&g_Zq[(size_t)(rowBase + r) * 128 + 64 + off];
        uint32_t dstA = sb + SM_A + r * ZSB + 64 + off;
        CP_ASYNC16(dstA, srcA);
        CP_ASYNC16(dstA + 16, srcA + 16);
        int rb = tid >> 2, offb = (tid & 3) * 16;
        const char* srcB = (const char*)&g_Zq[(size_t)(colBase + rb) * 128 + 64 + offb];
        CP_ASYNC16(sb + SM_B + rb * ZSB + 64 + offb, srcB);
    }
    CP_COMMIT();

    // scales into smem (regular loads; visible after the next __syncthreads)
    if (tid < 128) *(float*)(zsm + SM_SA + tid * 4) = g_Zs[rowBase + tid];
    else if (tid < 192) *(float*)(zsm + SM_SB + (tid - 128) * 4) = g_Zs[colBase + tid - 128];

    const int lr = lane & 15;
    const uint32_t lcB = (lane >> 4) * 16;  // byte offset within 32B k-chunk

    int acc1[2][4][4], acc2[2][4][4];
#pragma unroll
    for (int mt = 0; mt < 2; mt++)
#pragma unroll
        for (int nt = 0; nt < 4; nt++)
#pragma unroll
            for (int q = 0; q < 4; q++) { acc1[mt][nt][q] = 0; acc2[mt][nt][q] = 0; }

    const int ka_tab[6] = {0, 32, 0, 32, 64, 96};
    const int kb_tab[6] = {0, 32, 64, 96, 0, 32};

    CP_WAIT(1);
    __syncthreads();

#pragma unroll
    for (int s = 0; s < 6; s++) {
        if (s == 2) { CP_WAIT(0); __syncthreads(); }
        const int ka = ka_tab[s], kb = kb_tab[s];
        uint32_t a[2][4];
#pragma unroll
        for (int mt = 0; mt < 2; mt++) {
            uint32_t ad = sb + SM_A + (wm * 32 + mt * 16 + lr) * ZSB + ka + lcB;
            ldsm_x4(ad, a[mt][0], a[mt][1], a[mt][2], a[mt][3]);
        }
        uint32_t b[4][2];
#pragma unroll
        for (int np = 0; np < 2; np++) {
            uint32_t bd = sb + SM_B + (wn * 32 + np * 16 + lr) * ZSB + kb + lcB;
            uint32_t r0, r1, r2, r3;
            ldsm_x4(bd, r0, r1, r2, r3);
            b[2 * np][0] = r0; b[2 * np][1] = r2;
            b[2 * np + 1][0] = r1; b[2 * np + 1][1] = r3;
        }
#pragma unroll
        for (int mt = 0; mt < 2; mt++)
#pragma unroll
            for (int nt = 0; nt < 4; nt++) {
                if (s < 2)
                    imma16832(acc1[mt][nt], a[mt][0], a[mt][1], a[mt][2], a[mt][3],
                              b[nt][0], b[nt][1]);
                else
                    imma16832(acc2[mt][nt], a[mt][0], a[mt][1], a[mt][2], a[mt][3],
                              b[nt][0], b[nt][1]);
            }
    }

    // Epilogue: dequant + streaming stores (direct + mirror).
    const int qr = lane >> 2, qc = (lane & 3) * 2;
    const bool mirror = (bx >= 2 * by + 2);
    const float* sA = (const float*)(zsm + SM_SA);
    const float* sB = (const float*)(zsm + SM_SB);
#pragma unroll
    for (int mt = 0; mt < 2; mt++) {
        int rl0 = wm * 32 + mt * 16 + qr;
        float sr0 = sA[rl0], sr1 = sA[rl0 + 8];
        int r0 = rowBase + rl0;
#pragma unroll
        for (int nt = 0; nt < 4; nt++) {
            int cl = wn * 32 + nt * 8 + qc;
            float sc0 = sB[cl], sc1 = sB[cl + 1];
            int c = colBase + cl;
            float v00 = sr0 * sc0 * ((float)acc1[mt][nt][0] + (float)acc2[mt][nt][0] * 0.00390625f);
            float v01 = sr0 * sc1 * ((float)acc1[mt][nt][1] + (float)acc2[mt][nt][1] * 0.00390625f);
            float v10 = sr1 * sc0 * ((float)acc1[mt][nt][2] + (float)acc2[mt][nt][2] * 0.00390625f);
            float v11 = sr1 * sc1 * ((float)acc1[mt][nt][3] + (float)acc2[mt][nt][3] * 0.00390625f);
            __stcs((float2*)&out[(size_t)r0 * NN + c], make_float2(v00, v01));
            __stcs((float2*)&out[(size_t)(r0 + 8) * NN + c], make_float2(v10, v11));
            if (mirror) {
                __stcs(&out[(size_t)c * NN + r0], v00);
                __stcs(&out[(size_t)(c + 1) * NN + r0], v01);
                __stcs(&out[(size_t)c * NN + r0 + 8], v10);
                __stcs(&out[(size_t)(c + 1) * NN + r0 + 8], v11);
            }
        }
    }
}

// ---------------- launch ----------------
extern "C" void kernel_launch(void* const* d_in, const int* in_sizes, int n_in,
                              void* d_out, int out_size) {
    const float* features = (const float*)d_in[0];
    const float* W0       = (const float*)d_in[1];
    const float* Wm       = (const float*)d_in[2];
    const float* Ws       = (const float*)d_in[3];
    const float* noise    = (const float*)d_in[4];
    const void*  ei       = d_in[5];
    float*       out      = (float*)d_out;

    static cudaStream_t s2 = nullptr;
    static cudaEvent_t evFork = nullptr, evJoin = nullptr;
    if (s2 == nullptr) {
        cudaStreamCreateWithFlags(&s2, cudaStreamNonBlocking);
        cudaEventCreateWithFlags(&evFork, cudaEventDisableTiming);
        cudaEventCreateWithFlags(&evJoin, cudaEventDisableTiming);
        cudaFuncSetAttribute(k_zzt_imma, cudaFuncAttributeMaxDynamicSharedMemorySize,
                             SM_TOT);
    }

    cudaEventRecord(evFork, 0);
    cudaStreamWaitEvent(s2, evFork, 0);
    k_gemm_norm<FIN, 0><<<NN / 64, 256, 0, s2>>>(features, W0);
    cudaEventRecord(evJoin, s2);

    k_init<<<1, 64>>>((const int*)ei);
    k_count<<<(NE + 255) / 256, 256>>>(ei);
    k_scan<<<1, 1024>>>();
    k_fill<<<(NE + 255) / 256, 256>>>(ei);

    cudaStreamWaitEvent(0, evJoin, 0);
    k_agg1<<<NN / 8, 256>>>();
    k_gemm_norm<FH, 1><<<NN / 64, 256>>>(Wm, Ws);
    k_agg2z<<<NN / 8, 256>>>(noise);

    k_zzt_imma<<<NTRI8, 256, SM_TOT>>>(out);
}